// round 15
// baseline (speedup 1.0000x reference)
#include <cuda_runtime.h>
#include <cuda_fp16.h>
#include <math.h>
#include <stdint.h>

#define N_ENT 20000
#define DIM   200
#define RR    20
#define NB    20
#define NL    2
#define NT    2
#define NE    250000
#define NQ    8192
#define HID   256
#define D3    600

#define BM 128
#define EGRID 1973
#define EPADTOT (EGRID*BM)
#define MTILES 157
#define GNPAD 640
#define XROW 256              // halves per row (hi only, fp16 scaled)
#define NSLAB 7               // 7*32 = 224 >= 200

#define XS 64.0f
#define WS 2048.0f
#define SCALE_INV (1.0f/131072.0f)

// dynamic smem (bytes): A[3 stages][128 rows][80], B[3 stages][128][80], idx
#define A_STG 10240
#define OFF_B 30720
#define B_STG 10240
#define OFF_SRC 61440
#define OFF_RCV 61952
#define P_SMEM 62464

// ---------------- device scratch ----------------
__device__ __align__(16) float g_relw[NL*RR*DIM*DIM];
__device__ __align__(16) float g_h  [N_ENT*DIM];
__device__ __align__(16) float g_agg[N_ENT*DIM];
__device__ __align__(16) float g_xW [N_ENT*D3];
__device__ __align__(16) float g_hU [N_ENT*D3];
__device__ float g_deg[N_ENT];
__device__ float g_deginv[N_ENT];
__device__ int   g_perm[EPADTOT];
__device__ int   g_cnt[RR];
__device__ int   g_cur[RR];
__device__ __align__(16) __half g_hs [(size_t)N_ENT*XROW];
__device__ __align__(16) __half g_xs1[(size_t)N_ENT*XROW];
__device__ __align__(16) __half g_xs2[(size_t)N_ENT*XROW];
__device__ __align__(16) __half g_ws [(size_t)NL*RR*256*XROW];
__device__ __align__(16) __half g_sws[(size_t)NL*256*XROW];
__device__ __align__(16) __half g_gws[(size_t)GNPAD*XROW];
__device__ __align__(16) __half g_gus[(size_t)GNPAD*XROW];

// ---------------- helpers ----------------
__device__ __forceinline__ uint32_t smem_u32(const void* p) {
    uint32_t a;
    asm("{ .reg .u64 t; cvta.to.shared.u64 t, %1; cvt.u32.u64 %0, t; }" : "=r"(a) : "l"(p));
    return a;
}
__device__ __forceinline__ void mma16(float* c, const uint32_t* a, uint32_t b0, uint32_t b1) {
    asm volatile(
        "mma.sync.aligned.m16n8k16.row.col.f32.f16.f16.f32 "
        "{%0,%1,%2,%3}, {%4,%5,%6,%7}, {%8,%9}, {%0,%1,%2,%3};"
        : "+f"(c[0]), "+f"(c[1]), "+f"(c[2]), "+f"(c[3])
        : "r"(a[0]), "r"(a[1]), "r"(a[2]), "r"(a[3]), "r"(b0), "r"(b1));
}
__device__ __forceinline__ void ldx4(uint32_t* r, uint32_t addr) {
    asm volatile("ldmatrix.sync.aligned.m8n8.x4.shared.b16 {%0,%1,%2,%3}, [%4];"
        : "=r"(r[0]), "=r"(r[1]), "=r"(r[2]), "=r"(r[3]) : "r"(addr));
}
__device__ __forceinline__ void cpa16(uint32_t dst, const void* src) {
    asm volatile("cp.async.cg.shared.global [%0], [%1], 16;" :: "r"(dst), "l"(src) : "memory");
}
__device__ __forceinline__ void cpa_commit() {
    asm volatile("cp.async.commit_group;" ::: "memory");
}
__device__ __forceinline__ void cpa_wait1() {
    asm volatile("cp.async.wait_group 1;" ::: "memory");
}
__device__ __forceinline__ void cpa_wait0() {
    asm volatile("cp.async.wait_group 0;" ::: "memory");
}
__device__ __forceinline__ void red4(float* p, float a, float b, float c, float d) {
    asm volatile("red.global.add.v4.f32 [%0], {%1,%2,%3,%4};"
                 :: "l"(p), "f"(a), "f"(b), "f"(c), "f"(d) : "memory");
}
__device__ __forceinline__ float sigf(float x) { return 1.f / (1.f + expf(-x)); }

// one k32 slab of single-pass fp16 mma on stage st (C = Ah*Bh)
__device__ __forceinline__ void slab_mma(uint32_t sb, int st, int wm, int wn, int lane,
                                         int nlim, float (*acc)[4][4]) {
    if (wn >= nlim) return;   // warp-uniform: whole warp-tile dead
    uint32_t abase = sb + st*A_STG;
    uint32_t bbase = sb + OFF_B + st*B_STG;
    int rowoff = (lane & 15)*80 + ((lane >> 4)*16);
#pragma unroll
    for (int kk = 0; kk < 2; ++kk) {
        uint32_t aH[2][4], bH[2][4];
#pragma unroll
        for (int mi = 0; mi < 2; ++mi)
            ldx4(aH[mi], abase + (wm + mi*16)*80 + rowoff + kk*32);
#pragma unroll
        for (int nj2 = 0; nj2 < 2; ++nj2) {
            if (wn + nj2*16 < nlim)
                ldx4(bH[nj2], bbase + (wn + nj2*16)*80 + rowoff + kk*32);
        }
        // x4 on 16(n)x16(k): reg0=(n0-7,k0-7) reg1=(n8-15,k0-7) reg2=(n0-7,k8-15) reg3=(n8-15,k8-15)
#pragma unroll
        for (int mi = 0; mi < 2; ++mi)
#pragma unroll
            for (int nj = 0; nj < 4; ++nj) {
                if (wn + nj*8 >= nlim) continue;
                mma16(acc[mi][nj], aH[mi], bH[nj>>1][nj&1], bH[nj>>1][(nj&1)+2]);
            }
    }
}

// ---------------- small utility kernels ----------------
__global__ void k_zerof(float* p, int n) {
    int i = blockIdx.x*blockDim.x + threadIdx.x;
    for (; i < n; i += gridDim.x*blockDim.x) p[i] = 0.f;
}
__global__ void k_copy(float* dst, const float* src, int n) {
    int i = blockIdx.x*blockDim.x + threadIdx.x;
    for (; i < n; i += gridDim.x*blockDim.x) dst[i] = src[i];
}
// fused per-timestep setup: perm=-1, deg=0, cnt=0
__global__ void k_setup() {
    int i = blockIdx.x*blockDim.x + threadIdx.x;
    int stride = gridDim.x*blockDim.x;
    for (int j = i; j < EPADTOT; j += stride) g_perm[j] = -1;
    for (int j = i; j < N_ENT; j += stride) g_deg[j] = 0.f;
    if (i < RR) g_cnt[i] = 0;
}
// fused deg accumulation + relation histogram (one edge pass)
__global__ void k_prep(const int* __restrict__ rcv, const int* __restrict__ rel) {
    __shared__ int s_cnt[RR];
    int tid = threadIdx.x;
    if (tid < RR) s_cnt[tid] = 0;
    __syncthreads();
    int i = blockIdx.x*blockDim.x + tid;
    for (; i < NE; i += gridDim.x*blockDim.x) {
        atomicAdd(&g_deg[rcv[i]], 1.f);
        atomicAdd(&s_cnt[rel[i]], 1);
    }
    __syncthreads();
    if (tid < RR) atomicAdd(&g_cnt[tid], s_cnt[tid]);
}
// fused scan (block 0 thread 0) + deginv (all threads)
__global__ void k_scan_dinv() {
    if (blockIdx.x == 0 && threadIdx.x == 0) {
        int run = 0;
        for (int r = 0; r < RR; ++r) {
            g_cur[r] = run;
            run += ((g_cnt[r] + BM - 1) / BM) * BM;
        }
    }
    int i = blockIdx.x*blockDim.x + threadIdx.x;
    if (i < N_ENT) g_deginv[i] = 1.f / fmaxf(g_deg[i], 1.f);
}
__global__ void k_scatter(const int* __restrict__ rel) {
    int i = blockIdx.x*blockDim.x + threadIdx.x;
    for (; i < NE; i += gridDim.x*blockDim.x) {
        int r = rel[i];
        int p = atomicAdd(&g_cur[r], 1);
        g_perm[p] = i;
    }
}

__global__ void k_relw(const float* __restrict__ basis, const float* __restrict__ coeff) {
    __shared__ float s_co[NL*RR*NB];
    int tid = threadIdx.x;
    for (int i = tid; i < NL*RR*NB; i += blockDim.x) s_co[i] = coeff[i];
    __syncthreads();
    int gid = blockIdx.x*blockDim.x + tid;
    if (gid >= NL*DIM*DIM) return;
    int l = gid / (DIM*DIM);
    int rem = gid % (DIM*DIM);
    int i = rem / DIM, o = rem % DIM;
    float acc[RR];
#pragma unroll
    for (int r = 0; r < RR; ++r) acc[r] = 0.f;
    for (int b = 0; b < NB; ++b) {
        float bv = basis[((l*NB + b)*DIM + i)*DIM + o];
#pragma unroll
        for (int r = 0; r < RR; ++r) acc[r] += s_co[(l*RR + r)*NB + b] * bv;
    }
    for (int r = 0; r < RR; ++r)
        g_relw[((l*RR + r)*DIM + i)*DIM + o] = acc[r];
}

// transpose + scaled fp16: dst[b][n][k] = fp16(WS * src[b][k][n])
__global__ void k_splitw(const float* __restrict__ src, __half* __restrict__ dst,
                         int Nsrc, int Nvalid, size_t sstride, size_t dstride) {
    int b = blockIdx.z;
    int idx = blockIdx.x*blockDim.x + threadIdx.x;
    int n = idx >> 8, k = idx & 255;
    float v = 0.f;
    if (n < Nvalid && k < DIM) v = src[b*sstride + (size_t)k*Nsrc + n] * WS;
    dst[b*dstride + (size_t)n*XROW + k] = __float2half_rn(v);
}

__global__ void k_splitx(const float* __restrict__ src, __half* __restrict__ dst) {
    int idx = blockIdx.x*blockDim.x + threadIdx.x;
    if (idx >= N_ENT*256) return;
    int n = idx >> 8, c = idx & 255;
    float v = (c < DIM) ? src[(size_t)n*DIM + c] * XS : 0.f;
    dst[(size_t)n*XROW + c] = __float2half_rn(v);
}

// ---------------- edge gather-GEMM-scatter ----------------
__global__ void __launch_bounds__(512, 2)
k_edge(const __half* __restrict__ xs, const __half* __restrict__ wsl,
       const int* __restrict__ snd, const int* __restrict__ rcv,
       const int* __restrict__ relt) {
    extern __shared__ __align__(16) char sm[];
    uint32_t sb = smem_u32(sm);
    int* s_src = (int*)(sm + OFF_SRC);
    int* s_rcv = (int*)(sm + OFF_RCV);
    int tid = threadIdx.x, lane = tid & 31, w = tid >> 5;

    int e0 = g_perm[blockIdx.x*BM];
    if (e0 < 0) return;
    int rel = relt[e0];
    if (tid < BM) {
        int e = g_perm[blockIdx.x*BM + tid];
        int sv = 0, rv = -1;
        if (e >= 0) { sv = snd[e]; rv = rcv[e]; }
        s_src[tid] = sv; s_rcv[tid] = rv;
    }
    __syncthreads();

    const __half* wr = wsl + (size_t)rel * (256*XROW);
    int n0 = blockIdx.y * BM;
    int nlim = DIM - n0; if (nlim > BM) nlim = BM;
    int wm = (w & 3)*32, wn = (w >> 2)*32;
    int grp = lane >> 2, qid = lane & 3;

    float acc[2][4][4];
#pragma unroll
    for (int a = 0; a < 2; ++a)
#pragma unroll
        for (int b = 0; b < 4; ++b)
#pragma unroll
            for (int c = 0; c < 4; ++c) acc[a][b][c] = 0.f;

#define E_ISSUE(s, st)                                                           \
    {                                                                            \
        for (int j = tid; j < 1024; j += 512) {                                  \
            int row = (j >> 2) & 127, ch = j & 3;                                \
            if (j < 512) {                                                       \
                cpa16(sb + (st)*A_STG + row*80 + ch*16,                          \
                      xs + (size_t)s_src[row]*XROW + (s)*32 + ch*8);             \
            } else {                                                             \
                cpa16(sb + OFF_B + (st)*B_STG + row*80 + ch*16,                  \
                      wr + (size_t)(n0 + row)*XROW + (s)*32 + ch*8);             \
            }                                                                    \
        }                                                                        \
        cpa_commit();                                                            \
    }

    E_ISSUE(0, 0);
    E_ISSUE(1, 1);
#pragma unroll
    for (int s = 0; s < NSLAB; ++s) {
        if (s + 1 < NSLAB) cpa_wait1(); else cpa_wait0();
        __syncthreads();                        // single barrier per slab
        if (s + 2 < NSLAB) E_ISSUE(s + 2, (s + 2) % 3);
        slab_mma(sb, s % 3, wm, wn, lane, nlim, acc);
    }
#undef E_ISSUE

    // scatter epilogue: butterfly-shuffle to 4-consecutive cols, then red.v4
#pragma unroll
    for (int mi = 0; mi < 2; ++mi) {
        int r_e = wm + mi*16 + grp;
        int rv_e = s_rcv[r_e], rv_o = s_rcv[r_e + 8];
#pragma unroll
        for (int nj = 0; nj < 4; ++nj) {
            if (wn + nj*8 >= nlim) continue;
            float* c = acc[mi][nj];
            float e0f = __shfl_xor_sync(0xffffffffu, c[0], 1);
            float e1f = __shfl_xor_sync(0xffffffffu, c[1], 1);
            float e2f = __shfl_xor_sync(0xffffffffu, c[2], 1);
            float e3f = __shfl_xor_sync(0xffffffffu, c[3], 1);
            int colb = n0 + wn + nj*8 + (qid & ~1)*2;
            if ((qid & 1) == 0) {
                if (rv_e >= 0)
                    red4(g_agg + (size_t)rv_e*DIM + colb,
                         c[0]*SCALE_INV, c[1]*SCALE_INV, e0f*SCALE_INV, e1f*SCALE_INV);
            } else {
                if (rv_o >= 0)
                    red4(g_agg + (size_t)rv_o*DIM + colb,
                         e2f*SCALE_INV, e3f*SCALE_INV, c[2]*SCALE_INV, c[3]*SCALE_INV);
            }
        }
    }
}

// ---------------- dense GEMM ----------------
// mode 1 additionally RE-ZEROES agg after reading it (replaces separate zerof pass)
__global__ void __launch_bounds__(512, 2)
k_dense(const __half* __restrict__ Axs, const __half* __restrict__ Bws,
        int M, int mode, int Nvalid,
        float* __restrict__ C, int ldC,
        float* __restrict__ agg, const float* __restrict__ dinv,
        const float* __restrict__ bias, __half* __restrict__ out_xs) {
    extern __shared__ __align__(16) char sm[];
    uint32_t sb = smem_u32(sm);
    int tid = threadIdx.x, lane = tid & 31, w = tid >> 5;
    int m0 = blockIdx.x * BM;
    int n0 = blockIdx.y * BM;
    int nlim = Nvalid - n0; if (nlim > BM) nlim = BM; if (nlim < 0) nlim = 0;
    int wm = (w & 3)*32, wn = (w >> 2)*32;
    int grp = lane >> 2, qid = lane & 3;

    float acc[2][4][4];
#pragma unroll
    for (int a = 0; a < 2; ++a)
#pragma unroll
        for (int b = 0; b < 4; ++b)
#pragma unroll
            for (int c = 0; c < 4; ++c) acc[a][b][c] = 0.f;

#define D_ISSUE(s, st)                                                           \
    {                                                                            \
        for (int j = tid; j < 1024; j += 512) {                                  \
            int row = (j >> 2) & 127, ch = j & 3;                                \
            if (j < 512) {                                                       \
                int gm = m0 + row; if (gm >= M) gm = 0;                          \
                cpa16(sb + (st)*A_STG + row*80 + ch*16,                          \
                      Axs + (size_t)gm*XROW + (s)*32 + ch*8);                    \
            } else {                                                             \
                cpa16(sb + OFF_B + (st)*B_STG + row*80 + ch*16,                  \
                      Bws + (size_t)(n0 + row)*XROW + (s)*32 + ch*8);            \
            }                                                                    \
        }                                                                        \
        cpa_commit();                                                            \
    }

    D_ISSUE(0, 0);
    D_ISSUE(1, 1);
#pragma unroll
    for (int s = 0; s < NSLAB; ++s) {
        if (s + 1 < NSLAB) cpa_wait1(); else cpa_wait0();
        __syncthreads();
        if (s + 2 < NSLAB) D_ISSUE(s + 2, (s + 2) % 3);
        slab_mma(sb, s % 3, wm, wn, lane, nlim, acc);
    }
#undef D_ISSUE

#pragma unroll
    for (int mi = 0; mi < 2; ++mi) {
        int r0 = m0 + wm + mi*16 + grp;
        int r1 = r0 + 8;
#pragma unroll
        for (int nj = 0; nj < 4; ++nj) {
            if (wn + nj*8 >= nlim) continue;   // dead n-block: pad stays zero-init
            int col = n0 + wn + nj*8 + qid*2;
            float* c = acc[mi][nj];
            if (mode == 0) {
                if (col >= Nvalid) continue;
                if (r0 < M) *(float2*)(C + (size_t)r0*ldC + col) =
                    make_float2(c[0]*SCALE_INV, c[1]*SCALE_INV);
                if (r1 < M) *(float2*)(C + (size_t)r1*ldC + col) =
                    make_float2(c[2]*SCALE_INV, c[3]*SCALE_INV);
            } else {
#pragma unroll
                for (int h = 0; h < 2; ++h) {
                    int row = h ? r1 : r0;
                    if (row >= M) continue;
                    float v0 = 0.f, v1 = 0.f;
                    if (col < DIM) {
                        float dv = dinv[row];
                        float2 av = *(float2*)(agg + (size_t)row*DIM + col);
                        float a0 = av.x*dv + bias[col];
                        float a1 = av.y*dv + bias[col + 1];
                        v0 = fmaxf(c[h*2+0]*SCALE_INV + a0, 0.f) * XS;
                        v1 = fmaxf(c[h*2+1]*SCALE_INV + a1, 0.f) * XS;
                        *(float2*)(agg + (size_t)row*DIM + col) = make_float2(0.f, 0.f);
                    }
                    *(__half2*)(out_xs + (size_t)row*XROW + col) =
                        __halves2half2(__float2half_rn(v0), __float2half_rn(v1));
                }
            }
        }
    }
}

__global__ void k_gru(const float* __restrict__ bg) {
    int idx = blockIdx.x*blockDim.x + threadIdx.x;
    if (idx >= N_ENT*DIM) return;
    int n = idx / DIM, c = idx % DIM;
    size_t b = (size_t)n*D3;
    float r  = sigf(g_xW[b + c]        + g_hU[b + c]        + bg[c]);
    float z  = sigf(g_xW[b + DIM + c]  + g_hU[b + DIM + c]  + bg[DIM + c]);
    float hu3 = g_hU[b + 2*DIM + c];
    float ht = tanhf(g_xW[b + 2*DIM + c] + hu3 + bg[2*DIM + c] + r * hu3);
    float h0 = g_h[idx];
    float hn = (1.f - z)*h0 + z*ht;
    g_h[idx] = hn;
    g_hs[(size_t)n*XROW + c] = __float2half_rn(hn * XS);
}

__global__ void __launch_bounds__(256)
k_score(const int* __restrict__ triples, const float* __restrict__ rel_emb,
        const float* __restrict__ fc1, const float* __restrict__ b1,
        const float* __restrict__ fc2, const float* __restrict__ fc2b,
        float* __restrict__ out) {
    __shared__ float As[32][8];
    __shared__ float Bs[8][HID];
    __shared__ int s_s[32], s_r[32], s_o[32];
    int tid = threadIdx.x;
    int qbase = blockIdx.x * 32;
    if (tid < 32) {
        s_s[tid] = triples[(qbase + tid)*3 + 0];
        s_r[tid] = triples[(qbase + tid)*3 + 1];
        s_o[tid] = triples[(qbase + tid)*3 + 2];
    }
    __syncthreads();
    int w = tid >> 5, lane = tid & 31;
    float acc[4][8];
#pragma unroll
    for (int i = 0; i < 4; ++i)
#pragma unroll
        for (int j = 0; j < 8; ++j) acc[i][j] = 0.f;

    for (int k0 = 0; k0 < D3; k0 += 8) {
        {
            int qi = tid >> 3, kk = tid & 7, k = k0 + kk;
            float v;
            if (k < DIM)            v = g_h[(size_t)s_s[qi]*DIM + k];
            else if (k < 2*DIM)     v = rel_emb[(size_t)s_r[qi]*DIM + (k - DIM)];
            else                    v = g_h[(size_t)s_o[qi]*DIM + (k - 2*DIM)];
            As[qi][kk] = v;
        }
        {
            int kr = tid >> 5, cb = tid & 31;
#pragma unroll
            for (int j = 0; j < 8; ++j)
                Bs[kr][cb + 32*j] = fc1[(size_t)(k0 + kr)*HID + cb + 32*j];
        }
        __syncthreads();
#pragma unroll
        for (int kk = 0; kk < 8; ++kk) {
#pragma unroll
            for (int i = 0; i < 4; ++i) {
                float a = As[w*4 + i][kk];
#pragma unroll
                for (int j = 0; j < 8; ++j)
                    acc[i][j] += a * Bs[kk][lane + 32*j];
            }
        }
        __syncthreads();
    }
#pragma unroll
    for (int i = 0; i < 4; ++i) {
        float p = 0.f;
#pragma unroll
        for (int j = 0; j < 8; ++j) {
            int col = lane + 32*j;
            float hv = fmaxf(acc[i][j] + b1[col], 0.f);
            p += hv * fc2[col];
        }
#pragma unroll
        for (int off = 16; off > 0; off >>= 1)
            p += __shfl_down_sync(0xffffffffu, p, off);
        if (lane == 0) out[qbase + w*4 + i] = p + fc2b[0];
    }
}

// ---------------- host ----------------
extern "C" void kernel_launch(void* const* d_in, const int* in_sizes, int n_in,
                              void* d_out, int out_size) {
    const float* entity_emb = (const float*)d_in[0];
    const float* basis      = (const float*)d_in[1];
    const float* coeff      = (const float*)d_in[2];
    const float* self_w     = (const float*)d_in[3];
    const float* bias       = (const float*)d_in[4];
    const float* W_gates    = (const float*)d_in[5];
    const float* U_gates    = (const float*)d_in[6];
    const float* b_gates    = (const float*)d_in[7];
    const float* rel_emb    = (const float*)d_in[8];
    const float* fc1        = (const float*)d_in[9];
    const float* fc1_b      = (const float*)d_in[10];
    const float* fc2        = (const float*)d_in[11];
    const float* fc2_b      = (const float*)d_in[12];
    const int*   senders    = (const int*)d_in[13];
    const int*   receivers  = (const int*)d_in[14];
    const int*   rel_types  = (const int*)d_in[15];
    const int*   triples    = (const int*)d_in[16];
    float* out = (float*)d_out;

    cudaFuncSetAttribute(k_edge,  cudaFuncAttributeMaxDynamicSharedMemorySize, P_SMEM);
    cudaFuncSetAttribute(k_dense, cudaFuncAttributeMaxDynamicSharedMemorySize, P_SMEM);

    float *p_relw, *p_h, *p_agg, *p_dinv, *p_xW, *p_hU;
    __half *p_hs, *p_xs1, *p_xs2, *p_ws, *p_sws, *p_gws, *p_gus;
    cudaGetSymbolAddress((void**)&p_relw, g_relw);
    cudaGetSymbolAddress((void**)&p_h,    g_h);
    cudaGetSymbolAddress((void**)&p_agg,  g_agg);
    cudaGetSymbolAddress((void**)&p_dinv, g_deginv);
    cudaGetSymbolAddress((void**)&p_xW,   g_xW);
    cudaGetSymbolAddress((void**)&p_hU,   g_hU);
    cudaGetSymbolAddress((void**)&p_hs,   g_hs);
    cudaGetSymbolAddress((void**)&p_xs1,  g_xs1);
    cudaGetSymbolAddress((void**)&p_xs2,  g_xs2);
    cudaGetSymbolAddress((void**)&p_ws,   g_ws);
    cudaGetSymbolAddress((void**)&p_sws,  g_sws);
    cudaGetSymbolAddress((void**)&p_gws,  g_gws);
    cudaGetSymbolAddress((void**)&p_gus,  g_gus);

    k_relw<<<(NL*DIM*DIM + 255)/256, 256>>>(basis, coeff);
    k_splitw<<<dim3(256, 1, NL*RR), 256>>>(p_relw, p_ws, DIM, DIM,
                                           (size_t)DIM*DIM, (size_t)256*XROW);
    k_splitw<<<dim3(256, 1, NL), 256>>>(self_w, p_sws, DIM, DIM,
                                        (size_t)DIM*DIM, (size_t)256*XROW);
    k_splitw<<<dim3(GNPAD, 1, 1), 256>>>(W_gates, p_gws, D3, D3, 0, 0);
    k_splitw<<<dim3(GNPAD, 1, 1), 256>>>(U_gates, p_gus, D3, D3, 0, 0);
    k_splitx<<<(N_ENT*256 + 255)/256, 256>>>(entity_emb, p_hs);
    k_copy<<<1024, 256>>>(p_h, entity_emb, N_ENT*DIM);
    k_zerof<<<1024, 256>>>(p_agg, N_ENT*DIM);   // once; mode-1 dense re-zeroes thereafter

    for (int t = 0; t < NT; ++t) {
        const int* snd = senders   + (size_t)t*NE;
        const int* rcv = receivers + (size_t)t*NE;
        const int* rlt = rel_types + (size_t)t*NE;

        k_setup<<<512, 256>>>();
        k_prep<<<512, 256>>>(rcv, rlt);
        k_scan_dinv<<<(N_ENT + 255)/256, 256>>>();
        k_scatter<<<512, 256>>>(rlt);

        const __half* xin = p_hs;
        __half* xout[2] = { p_xs1, p_xs2 };
        for (int l = 0; l < NL; ++l) {
            k_edge<<<dim3(EGRID, 2), 512, P_SMEM>>>(xin, p_ws + (size_t)l*RR*256*XROW,
                                                    snd, rcv, rlt);
            k_dense<<<dim3(MTILES, 2), 512, P_SMEM>>>(
                xin, p_sws + (size_t)l*256*XROW, N_ENT, 1, DIM,
                nullptr, 0, p_agg, p_dinv, bias + (size_t)l*DIM, xout[l]);
            xin = xout[l];
        }
        k_dense<<<dim3(MTILES, 5), 512, P_SMEM>>>(
            p_xs2, p_gws, N_ENT, 0, D3, p_xW, D3, nullptr, nullptr, nullptr, nullptr);
        k_dense<<<dim3(MTILES, 5), 512, P_SMEM>>>(
            p_hs, p_gus, N_ENT, 0, D3, p_hU, D3, nullptr, nullptr, nullptr, nullptr);
        k_gru<<<(N_ENT*DIM + 255)/256, 256>>>(b_gates);
    }

    k_score<<<NQ/32, 256>>>(triples, rel_emb, fc1, fc1_b, fc2, fc2_b, out);
}

// round 16
// speedup vs baseline: 1.2357x; 1.2357x over previous
#include <cuda_runtime.h>
#include <cuda_fp16.h>
#include <math.h>
#include <stdint.h>

#define N_ENT 20000
#define DIM   200
#define RR    20
#define NB    20
#define NL    2
#define NT    2
#define NE    250000
#define NQ    8192
#define HID   256
#define D3    600

#define BM 128
#define EGRID 1973
#define EPADTOT (EGRID*BM)
#define MTILES 157
#define GNPAD 640
#define XROW 256              // halves per row (hi only, fp16 scaled)
#define NSLAB 7               // 7*32 = 224 >= 200

#define XS 64.0f
#define WS 2048.0f
#define SCALE_INV (1.0f/131072.0f)

// dynamic smem (bytes): A[3 stages][128 rows][80], B[3 stages][128][80], idx
#define A_STG 10240
#define OFF_B 30720
#define B_STG 10240
#define OFF_SRC 61440
#define OFF_RCV 61952
#define P_SMEM 62464

// ---------------- device scratch ----------------
__device__ __align__(16) float g_relw[NL*RR*DIM*DIM];
__device__ __align__(16) float g_h  [N_ENT*DIM];
__device__ __align__(16) float g_agg[N_ENT*DIM];
__device__ __align__(16) float g_xW [N_ENT*D3];
__device__ __align__(16) float g_hU [N_ENT*D3];
__device__ float g_deg[N_ENT];
__device__ float g_deginv[N_ENT];
__device__ int   g_perm[EPADTOT];
__device__ int   g_cnt[RR];
__device__ int   g_cur[RR];
__device__ __align__(16) __half g_hs [(size_t)N_ENT*XROW];
__device__ __align__(16) __half g_xs1[(size_t)N_ENT*XROW];
__device__ __align__(16) __half g_xs2[(size_t)N_ENT*XROW];
__device__ __align__(16) __half g_ws [(size_t)NL*RR*256*XROW];
__device__ __align__(16) __half g_sws[(size_t)NL*256*XROW];
__device__ __align__(16) __half g_gws[(size_t)GNPAD*XROW];
__device__ __align__(16) __half g_gus[(size_t)GNPAD*XROW];

// ---------------- helpers ----------------
__device__ __forceinline__ uint32_t smem_u32(const void* p) {
    uint32_t a;
    asm("{ .reg .u64 t; cvta.to.shared.u64 t, %1; cvt.u32.u64 %0, t; }" : "=r"(a) : "l"(p));
    return a;
}
__device__ __forceinline__ void mma16(float* c, const uint32_t* a, uint32_t b0, uint32_t b1) {
    asm volatile(
        "mma.sync.aligned.m16n8k16.row.col.f32.f16.f16.f32 "
        "{%0,%1,%2,%3}, {%4,%5,%6,%7}, {%8,%9}, {%0,%1,%2,%3};"
        : "+f"(c[0]), "+f"(c[1]), "+f"(c[2]), "+f"(c[3])
        : "r"(a[0]), "r"(a[1]), "r"(a[2]), "r"(a[3]), "r"(b0), "r"(b1));
}
__device__ __forceinline__ void ldx4(uint32_t* r, uint32_t addr) {
    asm volatile("ldmatrix.sync.aligned.m8n8.x4.shared.b16 {%0,%1,%2,%3}, [%4];"
        : "=r"(r[0]), "=r"(r[1]), "=r"(r[2]), "=r"(r[3]) : "r"(addr));
}
__device__ __forceinline__ void cpa16(uint32_t dst, const void* src) {
    asm volatile("cp.async.cg.shared.global [%0], [%1], 16;" :: "r"(dst), "l"(src) : "memory");
}
__device__ __forceinline__ void cpa_commit() {
    asm volatile("cp.async.commit_group;" ::: "memory");
}
__device__ __forceinline__ void cpa_wait1() {
    asm volatile("cp.async.wait_group 1;" ::: "memory");
}
__device__ __forceinline__ void cpa_wait0() {
    asm volatile("cp.async.wait_group 0;" ::: "memory");
}
__device__ __forceinline__ void red4(float* p, float a, float b, float c, float d) {
    asm volatile("red.global.add.v4.f32 [%0], {%1,%2,%3,%4};"
                 :: "l"(p), "f"(a), "f"(b), "f"(c), "f"(d) : "memory");
}
__device__ __forceinline__ float sigf(float x) { return 1.f / (1.f + expf(-x)); }

// one k32 slab of single-pass fp16 mma on stage st (C = Ah*Bh)
__device__ __forceinline__ void slab_mma(uint32_t sb, int st, int wm, int wn, int lane,
                                         int nlim, float (*acc)[4][4]) {
    if (wn >= nlim) return;   // warp-uniform: whole warp-tile dead
    uint32_t abase = sb + st*A_STG;
    uint32_t bbase = sb + OFF_B + st*B_STG;
    int rowoff = (lane & 15)*80 + ((lane >> 4)*16);
#pragma unroll
    for (int kk = 0; kk < 2; ++kk) {
        uint32_t aH[2][4], bH[2][4];
#pragma unroll
        for (int mi = 0; mi < 2; ++mi)
            ldx4(aH[mi], abase + (wm + mi*16)*80 + rowoff + kk*32);
#pragma unroll
        for (int nj2 = 0; nj2 < 2; ++nj2) {
            if (wn + nj2*16 < nlim)
                ldx4(bH[nj2], bbase + (wn + nj2*16)*80 + rowoff + kk*32);
        }
        // x4 on 16(n)x16(k): reg0=(n0-7,k0-7) reg1=(n8-15,k0-7) reg2=(n0-7,k8-15) reg3=(n8-15,k8-15)
#pragma unroll
        for (int mi = 0; mi < 2; ++mi)
#pragma unroll
            for (int nj = 0; nj < 4; ++nj) {
                if (wn + nj*8 >= nlim) continue;
                mma16(acc[mi][nj], aH[mi], bH[nj>>1][nj&1], bH[nj>>1][(nj&1)+2]);
            }
    }
}

// ---------------- small utility kernels ----------------
__global__ void k_zerof(float* p, int n) {
    int i = blockIdx.x*blockDim.x + threadIdx.x;
    for (; i < n; i += gridDim.x*blockDim.x) p[i] = 0.f;
}
__global__ void k_copy(float* dst, const float* src, int n) {
    int i = blockIdx.x*blockDim.x + threadIdx.x;
    for (; i < n; i += gridDim.x*blockDim.x) dst[i] = src[i];
}
// fused per-timestep setup: perm=-1, deg=0, cnt=0
__global__ void k_setup() {
    int i = blockIdx.x*blockDim.x + threadIdx.x;
    int stride = gridDim.x*blockDim.x;
    for (int j = i; j < EPADTOT; j += stride) g_perm[j] = -1;
    for (int j = i; j < N_ENT; j += stride) g_deg[j] = 0.f;
    if (i < RR) g_cnt[i] = 0;
}
// fused deg accumulation + relation histogram (one edge pass)
__global__ void k_prep(const int* __restrict__ rcv, const int* __restrict__ rel) {
    __shared__ int s_cnt[RR];
    int tid = threadIdx.x;
    if (tid < RR) s_cnt[tid] = 0;
    __syncthreads();
    int i = blockIdx.x*blockDim.x + tid;
    for (; i < NE; i += gridDim.x*blockDim.x) {
        atomicAdd(&g_deg[rcv[i]], 1.f);
        atomicAdd(&s_cnt[rel[i]], 1);
    }
    __syncthreads();
    if (tid < RR) atomicAdd(&g_cnt[tid], s_cnt[tid]);
}
// fused scan (block 0 thread 0) + deginv (all threads)
__global__ void k_scan_dinv() {
    if (blockIdx.x == 0 && threadIdx.x == 0) {
        int run = 0;
        for (int r = 0; r < RR; ++r) {
            g_cur[r] = run;
            run += ((g_cnt[r] + BM - 1) / BM) * BM;
        }
    }
    int i = blockIdx.x*blockDim.x + threadIdx.x;
    if (i < N_ENT) g_deginv[i] = 1.f / fmaxf(g_deg[i], 1.f);
}
__global__ void k_scatter(const int* __restrict__ rel) {
    int i = blockIdx.x*blockDim.x + threadIdx.x;
    for (; i < NE; i += gridDim.x*blockDim.x) {
        int r = rel[i];
        int p = atomicAdd(&g_cur[r], 1);
        g_perm[p] = i;
    }
}

__global__ void k_relw(const float* __restrict__ basis, const float* __restrict__ coeff) {
    __shared__ float s_co[NL*RR*NB];
    int tid = threadIdx.x;
    for (int i = tid; i < NL*RR*NB; i += blockDim.x) s_co[i] = coeff[i];
    __syncthreads();
    int gid = blockIdx.x*blockDim.x + tid;
    if (gid >= NL*DIM*DIM) return;
    int l = gid / (DIM*DIM);
    int rem = gid % (DIM*DIM);
    int i = rem / DIM, o = rem % DIM;
    float acc[RR];
#pragma unroll
    for (int r = 0; r < RR; ++r) acc[r] = 0.f;
    for (int b = 0; b < NB; ++b) {
        float bv = basis[((l*NB + b)*DIM + i)*DIM + o];
#pragma unroll
        for (int r = 0; r < RR; ++r) acc[r] += s_co[(l*RR + r)*NB + b] * bv;
    }
    for (int r = 0; r < RR; ++r)
        g_relw[((l*RR + r)*DIM + i)*DIM + o] = acc[r];
}

// transpose + scaled fp16: dst[b][n][k] = fp16(WS * src[b][k][n])
__global__ void k_splitw(const float* __restrict__ src, __half* __restrict__ dst,
                         int Nsrc, int Nvalid, size_t sstride, size_t dstride) {
    int b = blockIdx.z;
    int idx = blockIdx.x*blockDim.x + threadIdx.x;
    int n = idx >> 8, k = idx & 255;
    float v = 0.f;
    if (n < Nvalid && k < DIM) v = src[b*sstride + (size_t)k*Nsrc + n] * WS;
    dst[b*dstride + (size_t)n*XROW + k] = __float2half_rn(v);
}

__global__ void k_splitx(const float* __restrict__ src, __half* __restrict__ dst) {
    int idx = blockIdx.x*blockDim.x + threadIdx.x;
    if (idx >= N_ENT*256) return;
    int n = idx >> 8, c = idx & 255;
    float v = (c < DIM) ? src[(size_t)n*DIM + c] * XS : 0.f;
    dst[(size_t)n*XROW + c] = __float2half_rn(v);
}

// ---------------- edge gather-GEMM-scatter ----------------
__global__ void __launch_bounds__(512, 2)
k_edge(const __half* __restrict__ xs, const __half* __restrict__ wsl,
       const int* __restrict__ snd, const int* __restrict__ rcv,
       const int* __restrict__ relt) {
    extern __shared__ __align__(16) char sm[];
    uint32_t sb = smem_u32(sm);
    int* s_src = (int*)(sm + OFF_SRC);
    int* s_rcv = (int*)(sm + OFF_RCV);
    int tid = threadIdx.x, lane = tid & 31, w = tid >> 5;

    int e0 = g_perm[blockIdx.x*BM];
    if (e0 < 0) return;
    int rel = relt[e0];
    if (tid < BM) {
        int e = g_perm[blockIdx.x*BM + tid];
        int sv = 0, rv = -1;
        if (e >= 0) { sv = snd[e]; rv = rcv[e]; }
        s_src[tid] = sv; s_rcv[tid] = rv;
    }
    __syncthreads();

    const __half* wr = wsl + (size_t)rel * (256*XROW);
    int n0 = blockIdx.y * BM;
    int nlim = DIM - n0; if (nlim > BM) nlim = BM;
    int wm = (w & 3)*32, wn = (w >> 2)*32;
    int grp = lane >> 2, qid = lane & 3;

    float acc[2][4][4];
#pragma unroll
    for (int a = 0; a < 2; ++a)
#pragma unroll
        for (int b = 0; b < 4; ++b)
#pragma unroll
            for (int c = 0; c < 4; ++c) acc[a][b][c] = 0.f;

#define E_ISSUE(s, st)                                                           \
    {                                                                            \
        for (int j = tid; j < 1024; j += 512) {                                  \
            int row = (j >> 2) & 127, ch = j & 3;                                \
            if (j < 512) {                                                       \
                cpa16(sb + (st)*A_STG + row*80 + ch*16,                          \
                      xs + (size_t)s_src[row]*XROW + (s)*32 + ch*8);             \
            } else {                                                             \
                cpa16(sb + OFF_B + (st)*B_STG + row*80 + ch*16,                  \
                      wr + (size_t)(n0 + row)*XROW + (s)*32 + ch*8);             \
            }                                                                    \
        }                                                                        \
        cpa_commit();                                                            \
    }

    E_ISSUE(0, 0);
    E_ISSUE(1, 1);
#pragma unroll
    for (int s = 0; s < NSLAB; ++s) {
        if (s + 1 < NSLAB) cpa_wait1(); else cpa_wait0();
        __syncthreads();                        // single barrier per slab
        if (s + 2 < NSLAB) E_ISSUE(s + 2, (s + 2) % 3);
        slab_mma(sb, s % 3, wm, wn, lane, nlim, acc);
    }
#undef E_ISSUE

    // scatter epilogue: butterfly-shuffle to 4-consecutive cols, then red.v4
#pragma unroll
    for (int mi = 0; mi < 2; ++mi) {
        int r_e = wm + mi*16 + grp;
        int rv_e = s_rcv[r_e], rv_o = s_rcv[r_e + 8];
#pragma unroll
        for (int nj = 0; nj < 4; ++nj) {
            if (wn + nj*8 >= nlim) continue;
            float* c = acc[mi][nj];
            float e0f = __shfl_xor_sync(0xffffffffu, c[0], 1);
            float e1f = __shfl_xor_sync(0xffffffffu, c[1], 1);
            float e2f = __shfl_xor_sync(0xffffffffu, c[2], 1);
            float e3f = __shfl_xor_sync(0xffffffffu, c[3], 1);
            int colb = n0 + wn + nj*8 + (qid & ~1)*2;
            if ((qid & 1) == 0) {
                if (rv_e >= 0)
                    red4(g_agg + (size_t)rv_e*DIM + colb,
                         c[0]*SCALE_INV, c[1]*SCALE_INV, e0f*SCALE_INV, e1f*SCALE_INV);
            } else {
                if (rv_o >= 0)
                    red4(g_agg + (size_t)rv_o*DIM + colb,
                         e2f*SCALE_INV, e3f*SCALE_INV, c[2]*SCALE_INV, c[3]*SCALE_INV);
            }
        }
    }
}

// ---------------- dense GEMM ----------------
// blockIdx.z selects operand set (Axs/Bws/C vs Axs2/Bws2/C2) — used to fuse
// the two gate GEMMs into one launch. mode/epilogue identical to R13.
__global__ void __launch_bounds__(512, 2)
k_dense(const __half* __restrict__ Axs, const __half* __restrict__ Bws,
        const __half* __restrict__ Axs2, const __half* __restrict__ Bws2,
        int M, int mode, int Nvalid,
        float* __restrict__ C, float* __restrict__ C2, int ldC,
        const float* __restrict__ agg, const float* __restrict__ dinv,
        const float* __restrict__ bias, __half* __restrict__ out_xs) {
    extern __shared__ __align__(16) char sm[];
    uint32_t sb = smem_u32(sm);
    if (blockIdx.z) { Axs = Axs2; Bws = Bws2; C = C2; }
    int tid = threadIdx.x, lane = tid & 31, w = tid >> 5;
    int m0 = blockIdx.x * BM;
    int n0 = blockIdx.y * BM;
    int nlim = Nvalid - n0; if (nlim > BM) nlim = BM; if (nlim < 0) nlim = 0;
    int wm = (w & 3)*32, wn = (w >> 2)*32;
    int grp = lane >> 2, qid = lane & 3;

    float acc[2][4][4];
#pragma unroll
    for (int a = 0; a < 2; ++a)
#pragma unroll
        for (int b = 0; b < 4; ++b)
#pragma unroll
            for (int c = 0; c < 4; ++c) acc[a][b][c] = 0.f;

#define D_ISSUE(s, st)                                                           \
    {                                                                            \
        for (int j = tid; j < 1024; j += 512) {                                  \
            int row = (j >> 2) & 127, ch = j & 3;                                \
            if (j < 512) {                                                       \
                int gm = m0 + row; if (gm >= M) gm = 0;                          \
                cpa16(sb + (st)*A_STG + row*80 + ch*16,                          \
                      Axs + (size_t)gm*XROW + (s)*32 + ch*8);                    \
            } else {                                                             \
                cpa16(sb + OFF_B + (st)*B_STG + row*80 + ch*16,                  \
                      Bws + (size_t)(n0 + row)*XROW + (s)*32 + ch*8);            \
            }                                                                    \
        }                                                                        \
        cpa_commit();                                                            \
    }

    D_ISSUE(0, 0);
    D_ISSUE(1, 1);
#pragma unroll
    for (int s = 0; s < NSLAB; ++s) {
        if (s + 1 < NSLAB) cpa_wait1(); else cpa_wait0();
        __syncthreads();
        if (s + 2 < NSLAB) D_ISSUE(s + 2, (s + 2) % 3);
        slab_mma(sb, s % 3, wm, wn, lane, nlim, acc);
    }
#undef D_ISSUE

#pragma unroll
    for (int mi = 0; mi < 2; ++mi) {
        int r0 = m0 + wm + mi*16 + grp;
        int r1 = r0 + 8;
#pragma unroll
        for (int nj = 0; nj < 4; ++nj) {
            if (wn + nj*8 >= nlim) continue;   // dead n-block: pad stays zero-init
            int col = n0 + wn + nj*8 + qid*2;
            float* c = acc[mi][nj];
            if (mode == 0) {
                if (col >= Nvalid) continue;
                if (r0 < M) *(float2*)(C + (size_t)r0*ldC + col) =
                    make_float2(c[0]*SCALE_INV, c[1]*SCALE_INV);
                if (r1 < M) *(float2*)(C + (size_t)r1*ldC + col) =
                    make_float2(c[2]*SCALE_INV, c[3]*SCALE_INV);
            } else {
#pragma unroll
                for (int h = 0; h < 2; ++h) {
                    int row = h ? r1 : r0;
                    if (row >= M) continue;
                    float v0 = 0.f, v1 = 0.f;
                    if (col < DIM) {
                        float dv = dinv[row];
                        float a0 = agg[(size_t)row*DIM + col]*dv + bias[col];
                        float a1 = agg[(size_t)row*DIM + col + 1]*dv + bias[col + 1];
                        v0 = fmaxf(c[h*2+0]*SCALE_INV + a0, 0.f) * XS;
                        v1 = fmaxf(c[h*2+1]*SCALE_INV + a1, 0.f) * XS;
                    }
                    *(__half2*)(out_xs + (size_t)row*XROW + col) =
                        __halves2half2(__float2half_rn(v0), __float2half_rn(v1));
                }
            }
        }
    }
}

__global__ void k_gru(const float* __restrict__ bg) {
    int idx = blockIdx.x*blockDim.x + threadIdx.x;
    if (idx >= N_ENT*DIM) return;
    int n = idx / DIM, c = idx % DIM;
    size_t b = (size_t)n*D3;
    float r  = sigf(g_xW[b + c]        + g_hU[b + c]        + bg[c]);
    float z  = sigf(g_xW[b + DIM + c]  + g_hU[b + DIM + c]  + bg[DIM + c]);
    float hu3 = g_hU[b + 2*DIM + c];
    float ht = tanhf(g_xW[b + 2*DIM + c] + hu3 + bg[2*DIM + c] + r * hu3);
    float h0 = g_h[idx];
    float hn = (1.f - z)*h0 + z*ht;
    g_h[idx] = hn;
    g_hs[(size_t)n*XROW + c] = __float2half_rn(hn * XS);
}

__global__ void __launch_bounds__(256)
k_score(const int* __restrict__ triples, const float* __restrict__ rel_emb,
        const float* __restrict__ fc1, const float* __restrict__ b1,
        const float* __restrict__ fc2, const float* __restrict__ fc2b,
        float* __restrict__ out) {
    __shared__ float As[32][8];
    __shared__ float Bs[8][HID];
    __shared__ int s_s[32], s_r[32], s_o[32];
    int tid = threadIdx.x;
    int qbase = blockIdx.x * 32;
    if (tid < 32) {
        s_s[tid] = triples[(qbase + tid)*3 + 0];
        s_r[tid] = triples[(qbase + tid)*3 + 1];
        s_o[tid] = triples[(qbase + tid)*3 + 2];
    }
    __syncthreads();
    int w = tid >> 5, lane = tid & 31;
    float acc[4][8];
#pragma unroll
    for (int i = 0; i < 4; ++i)
#pragma unroll
        for (int j = 0; j < 8; ++j) acc[i][j] = 0.f;

    for (int k0 = 0; k0 < D3; k0 += 8) {
        {
            int qi = tid >> 3, kk = tid & 7, k = k0 + kk;
            float v;
            if (k < DIM)            v = g_h[(size_t)s_s[qi]*DIM + k];
            else if (k < 2*DIM)     v = rel_emb[(size_t)s_r[qi]*DIM + (k - DIM)];
            else                    v = g_h[(size_t)s_o[qi]*DIM + (k - 2*DIM)];
            As[qi][kk] = v;
        }
        {
            int kr = tid >> 5, cb = tid & 31;
#pragma unroll
            for (int j = 0; j < 8; ++j)
                Bs[kr][cb + 32*j] = fc1[(size_t)(k0 + kr)*HID + cb + 32*j];
        }
        __syncthreads();
#pragma unroll
        for (int kk = 0; kk < 8; ++kk) {
#pragma unroll
            for (int i = 0; i < 4; ++i) {
                float a = As[w*4 + i][kk];
#pragma unroll
                for (int j = 0; j < 8; ++j)
                    acc[i][j] += a * Bs[kk][lane + 32*j];
            }
        }
        __syncthreads();
    }
#pragma unroll
    for (int i = 0; i < 4; ++i) {
        float p = 0.f;
#pragma unroll
        for (int j = 0; j < 8; ++j) {
            int col = lane + 32*j;
            float hv = fmaxf(acc[i][j] + b1[col], 0.f);
            p += hv * fc2[col];
        }
#pragma unroll
        for (int off = 16; off > 0; off >>= 1)
            p += __shfl_down_sync(0xffffffffu, p, off);
        if (lane == 0) out[qbase + w*4 + i] = p + fc2b[0];
    }
}

// ---------------- host ----------------
extern "C" void kernel_launch(void* const* d_in, const int* in_sizes, int n_in,
                              void* d_out, int out_size) {
    const float* entity_emb = (const float*)d_in[0];
    const float* basis      = (const float*)d_in[1];
    const float* coeff      = (const float*)d_in[2];
    const float* self_w     = (const float*)d_in[3];
    const float* bias       = (const float*)d_in[4];
    const float* W_gates    = (const float*)d_in[5];
    const float* U_gates    = (const float*)d_in[6];
    const float* b_gates    = (const float*)d_in[7];
    const float* rel_emb    = (const float*)d_in[8];
    const float* fc1        = (const float*)d_in[9];
    const float* fc1_b      = (const float*)d_in[10];
    const float* fc2        = (const float*)d_in[11];
    const float* fc2_b      = (const float*)d_in[12];
    const int*   senders    = (const int*)d_in[13];
    const int*   receivers  = (const int*)d_in[14];
    const int*   rel_types  = (const int*)d_in[15];
    const int*   triples    = (const int*)d_in[16];
    float* out = (float*)d_out;

    cudaFuncSetAttribute(k_edge,  cudaFuncAttributeMaxDynamicSharedMemorySize, P_SMEM);
    cudaFuncSetAttribute(k_dense, cudaFuncAttributeMaxDynamicSharedMemorySize, P_SMEM);

    float *p_relw, *p_h, *p_agg, *p_dinv, *p_xW, *p_hU;
    __half *p_hs, *p_xs1, *p_xs2, *p_ws, *p_sws, *p_gws, *p_gus;
    cudaGetSymbolAddress((void**)&p_relw, g_relw);
    cudaGetSymbolAddress((void**)&p_h,    g_h);
    cudaGetSymbolAddress((void**)&p_agg,  g_agg);
    cudaGetSymbolAddress((void**)&p_dinv, g_deginv);
    cudaGetSymbolAddress((void**)&p_xW,   g_xW);
    cudaGetSymbolAddress((void**)&p_hU,   g_hU);
    cudaGetSymbolAddress((void**)&p_hs,   g_hs);
    cudaGetSymbolAddress((void**)&p_xs1,  g_xs1);
    cudaGetSymbolAddress((void**)&p_xs2,  g_xs2);
    cudaGetSymbolAddress((void**)&p_ws,   g_ws);
    cudaGetSymbolAddress((void**)&p_sws,  g_sws);
    cudaGetSymbolAddress((void**)&p_gws,  g_gws);
    cudaGetSymbolAddress((void**)&p_gus,  g_gus);

    k_relw<<<(NL*DIM*DIM + 255)/256, 256>>>(basis, coeff);
    k_splitw<<<dim3(256, 1, NL*RR), 256>>>(p_relw, p_ws, DIM, DIM,
                                           (size_t)DIM*DIM, (size_t)256*XROW);
    k_splitw<<<dim3(256, 1, NL), 256>>>(self_w, p_sws, DIM, DIM,
                                        (size_t)DIM*DIM, (size_t)256*XROW);
    k_splitw<<<dim3(GNPAD, 1, 1), 256>>>(W_gates, p_gws, D3, D3, 0, 0);
    k_splitw<<<dim3(GNPAD, 1, 1), 256>>>(U_gates, p_gus, D3, D3, 0, 0);
    k_splitx<<<(N_ENT*256 + 255)/256, 256>>>(entity_emb, p_hs);
    k_copy<<<1024, 256>>>(p_h, entity_emb, N_ENT*DIM);

    for (int t = 0; t < NT; ++t) {
        const int* snd = senders   + (size_t)t*NE;
        const int* rcv = receivers + (size_t)t*NE;
        const int* rlt = rel_types + (size_t)t*NE;

        k_setup<<<512, 256>>>();
        k_prep<<<512, 256>>>(rcv, rlt);
        k_scan_dinv<<<(N_ENT + 255)/256, 256>>>();
        k_scatter<<<512, 256>>>(rlt);

        const __half* xin = p_hs;
        __half* xout[2] = { p_xs1, p_xs2 };
        for (int l = 0; l < NL; ++l) {
            k_zerof<<<1024, 256>>>(p_agg, N_ENT*DIM);
            k_edge<<<dim3(EGRID, 2), 512, P_SMEM>>>(xin, p_ws + (size_t)l*RR*256*XROW,
                                                    snd, rcv, rlt);
            k_dense<<<dim3(MTILES, 2), 512, P_SMEM>>>(
                xin, p_sws + (size_t)l*256*XROW, xin, p_sws + (size_t)l*256*XROW,
                N_ENT, 1, DIM,
                nullptr, nullptr, 0, p_agg, p_dinv, bias + (size_t)l*DIM, xout[l]);
            xin = xout[l];
        }
        // gates: both GEMMs in one launch (z=0: x@W -> xW ; z=1: h@U -> hU)
        k_dense<<<dim3(MTILES, 5, 2), 512, P_SMEM>>>(
            p_xs2, p_gws, p_hs, p_gus, N_ENT, 0, D3,
            p_xW, p_hU, D3, nullptr, nullptr, nullptr, nullptr);
        k_gru<<<(N_ENT*DIM + 255)/256, 256>>>(b_gates);
    }

    k_score<<<NQ/32, 256>>>(triples, rel_emb, fc1, fc1_b, fc2, fc2_b, out);
}

// round 17
// speedup vs baseline: 1.3149x; 1.0641x over previous
#include <cuda_runtime.h>
#include <cuda_fp16.h>
#include <math.h>
#include <stdint.h>

#define N_ENT 20000
#define DIM   200
#define RR    20
#define NB    20
#define NL    2
#define NT    2
#define NE    250000
#define NQ    8192
#define HID   256
#define D3    600

#define BM 128
#define EGRID 1973
#define EPADTOT (EGRID*BM)
#define MTILES 157
#define GNPAD 640
#define XROW 256              // halves per row (hi only, fp16 scaled)
#define NSLAB 7               // 7*32 = 224 >= 200
#define FROW 768              // fc1^T row: 3 segments x 256
#define SSLAB 24              // score k-slabs

#define XS 64.0f
#define WS 2048.0f
#define SCALE_INV (1.0f/131072.0f)

// dynamic smem (bytes): A[3 stages][128 rows][80], B[3 stages][128][80], idx
#define A_STG 10240
#define OFF_B 30720
#define B_STG 10240
#define OFF_SRC 61440
#define OFF_RCV 61952
#define P_SMEM 62464
// score variant: 3 idx arrays
#define OFF_I0 61440
#define OFF_I1 61952
#define OFF_I2 62464
#define S_SMEM 62976

// ---------------- device scratch ----------------
__device__ __align__(16) float g_relw[NL*RR*DIM*DIM];
__device__ __align__(16) float g_h  [N_ENT*DIM];
__device__ __align__(16) float g_agg[N_ENT*DIM];
__device__ __align__(16) float g_xW [N_ENT*D3];
__device__ __align__(16) float g_hU [N_ENT*D3];
__device__ float g_deg[N_ENT];
__device__ float g_deginv[N_ENT];
__device__ int   g_perm[EPADTOT];
__device__ int   g_cnt[RR];
__device__ int   g_cur[RR];
__device__ __align__(16) __half g_hs [(size_t)N_ENT*XROW];
__device__ __align__(16) __half g_xs1[(size_t)N_ENT*XROW];
__device__ __align__(16) __half g_xs2[(size_t)N_ENT*XROW];
__device__ __align__(16) __half g_ws [(size_t)NL*RR*256*XROW];
__device__ __align__(16) __half g_sws[(size_t)NL*256*XROW];
__device__ __align__(16) __half g_gws[(size_t)GNPAD*XROW];
__device__ __align__(16) __half g_gus[(size_t)GNPAD*XROW];
__device__ __align__(16) __half g_rs [RR*XROW];          // rel_emb fp16 scaled
__device__ __align__(16) __half g_f1s[(size_t)HID*FROW]; // fc1^T fp16 scaled

// ---------------- helpers ----------------
__device__ __forceinline__ uint32_t smem_u32(const void* p) {
    uint32_t a;
    asm("{ .reg .u64 t; cvta.to.shared.u64 t, %1; cvt.u32.u64 %0, t; }" : "=r"(a) : "l"(p));
    return a;
}
__device__ __forceinline__ void mma16(float* c, const uint32_t* a, uint32_t b0, uint32_t b1) {
    asm volatile(
        "mma.sync.aligned.m16n8k16.row.col.f32.f16.f16.f32 "
        "{%0,%1,%2,%3}, {%4,%5,%6,%7}, {%8,%9}, {%0,%1,%2,%3};"
        : "+f"(c[0]), "+f"(c[1]), "+f"(c[2]), "+f"(c[3])
        : "r"(a[0]), "r"(a[1]), "r"(a[2]), "r"(a[3]), "r"(b0), "r"(b1));
}
__device__ __forceinline__ void ldx4(uint32_t* r, uint32_t addr) {
    asm volatile("ldmatrix.sync.aligned.m8n8.x4.shared.b16 {%0,%1,%2,%3}, [%4];"
        : "=r"(r[0]), "=r"(r[1]), "=r"(r[2]), "=r"(r[3]) : "r"(addr));
}
__device__ __forceinline__ void cpa16(uint32_t dst, const void* src) {
    asm volatile("cp.async.cg.shared.global [%0], [%1], 16;" :: "r"(dst), "l"(src) : "memory");
}
__device__ __forceinline__ void cpa_commit() {
    asm volatile("cp.async.commit_group;" ::: "memory");
}
__device__ __forceinline__ void cpa_wait1() {
    asm volatile("cp.async.wait_group 1;" ::: "memory");
}
__device__ __forceinline__ void cpa_wait0() {
    asm volatile("cp.async.wait_group 0;" ::: "memory");
}
__device__ __forceinline__ void red4(float* p, float a, float b, float c, float d) {
    asm volatile("red.global.add.v4.f32 [%0], {%1,%2,%3,%4};"
                 :: "l"(p), "f"(a), "f"(b), "f"(c), "f"(d) : "memory");
}
__device__ __forceinline__ float sigf(float x) { return 1.f / (1.f + expf(-x)); }

// one k32 slab of single-pass fp16 mma on stage st (C = Ah*Bh)
__device__ __forceinline__ void slab_mma(uint32_t sb, int st, int wm, int wn, int lane,
                                         int nlim, float (*acc)[4][4]) {
    if (wn >= nlim) return;
    uint32_t abase = sb + st*A_STG;
    uint32_t bbase = sb + OFF_B + st*B_STG;
    int rowoff = (lane & 15)*80 + ((lane >> 4)*16);
#pragma unroll
    for (int kk = 0; kk < 2; ++kk) {
        uint32_t aH[2][4], bH[2][4];
#pragma unroll
        for (int mi = 0; mi < 2; ++mi)
            ldx4(aH[mi], abase + (wm + mi*16)*80 + rowoff + kk*32);
#pragma unroll
        for (int nj2 = 0; nj2 < 2; ++nj2) {
            if (wn + nj2*16 < nlim)
                ldx4(bH[nj2], bbase + (wn + nj2*16)*80 + rowoff + kk*32);
        }
#pragma unroll
        for (int mi = 0; mi < 2; ++mi)
#pragma unroll
            for (int nj = 0; nj < 4; ++nj) {
                if (wn + nj*8 >= nlim) continue;
                mma16(acc[mi][nj], aH[mi], bH[nj>>1][nj&1], bH[nj>>1][(nj&1)+2]);
            }
    }
}

// ---------------- small utility kernels ----------------
__global__ void k_zerof(float* p, int n) {
    int i = blockIdx.x*blockDim.x + threadIdx.x;
    for (; i < n; i += gridDim.x*blockDim.x) p[i] = 0.f;
}
__global__ void k_copy(float* dst, const float* src, int n) {
    int i = blockIdx.x*blockDim.x + threadIdx.x;
    for (; i < n; i += gridDim.x*blockDim.x) dst[i] = src[i];
}
__global__ void k_setup() {
    int i = blockIdx.x*blockDim.x + threadIdx.x;
    int stride = gridDim.x*blockDim.x;
    for (int j = i; j < EPADTOT; j += stride) g_perm[j] = -1;
    for (int j = i; j < N_ENT; j += stride) g_deg[j] = 0.f;
    if (i < RR) g_cnt[i] = 0;
}
__global__ void k_prep(const int* __restrict__ rcv, const int* __restrict__ rel) {
    __shared__ int s_cnt[RR];
    int tid = threadIdx.x;
    if (tid < RR) s_cnt[tid] = 0;
    __syncthreads();
    int i = blockIdx.x*blockDim.x + tid;
    for (; i < NE; i += gridDim.x*blockDim.x) {
        atomicAdd(&g_deg[rcv[i]], 1.f);
        atomicAdd(&s_cnt[rel[i]], 1);
    }
    __syncthreads();
    if (tid < RR) atomicAdd(&g_cnt[tid], s_cnt[tid]);
}
__global__ void k_scan_dinv() {
    if (blockIdx.x == 0 && threadIdx.x == 0) {
        int run = 0;
        for (int r = 0; r < RR; ++r) {
            g_cur[r] = run;
            run += ((g_cnt[r] + BM - 1) / BM) * BM;
        }
    }
    int i = blockIdx.x*blockDim.x + threadIdx.x;
    if (i < N_ENT) g_deginv[i] = 1.f / fmaxf(g_deg[i], 1.f);
}
__global__ void k_scatter(const int* __restrict__ rel) {
    int i = blockIdx.x*blockDim.x + threadIdx.x;
    for (; i < NE; i += gridDim.x*blockDim.x) {
        int r = rel[i];
        int p = atomicAdd(&g_cur[r], 1);
        g_perm[p] = i;
    }
}

__global__ void k_relw(const float* __restrict__ basis, const float* __restrict__ coeff) {
    __shared__ float s_co[NL*RR*NB];
    int tid = threadIdx.x;
    for (int i = tid; i < NL*RR*NB; i += blockDim.x) s_co[i] = coeff[i];
    __syncthreads();
    int gid = blockIdx.x*blockDim.x + tid;
    if (gid >= NL*DIM*DIM) return;
    int l = gid / (DIM*DIM);
    int rem = gid % (DIM*DIM);
    int i = rem / DIM, o = rem % DIM;
    float acc[RR];
#pragma unroll
    for (int r = 0; r < RR; ++r) acc[r] = 0.f;
    for (int b = 0; b < NB; ++b) {
        float bv = basis[((l*NB + b)*DIM + i)*DIM + o];
#pragma unroll
        for (int r = 0; r < RR; ++r) acc[r] += s_co[(l*RR + r)*NB + b] * bv;
    }
    for (int r = 0; r < RR; ++r)
        g_relw[((l*RR + r)*DIM + i)*DIM + o] = acc[r];
}

__global__ void k_splitw(const float* __restrict__ src, __half* __restrict__ dst,
                         int Nsrc, int Nvalid, size_t sstride, size_t dstride) {
    int b = blockIdx.z;
    int idx = blockIdx.x*blockDim.x + threadIdx.x;
    int n = idx >> 8, k = idx & 255;
    float v = 0.f;
    if (n < Nvalid && k < DIM) v = src[b*sstride + (size_t)k*Nsrc + n] * WS;
    dst[b*dstride + (size_t)n*XROW + k] = __float2half_rn(v);
}

__global__ void k_splitx(const float* __restrict__ src, __half* __restrict__ dst) {
    int idx = blockIdx.x*blockDim.x + threadIdx.x;
    if (idx >= N_ENT*256) return;
    int n = idx >> 8, c = idx & 255;
    float v = (c < DIM) ? src[(size_t)n*DIM + c] * XS : 0.f;
    dst[(size_t)n*XROW + c] = __float2half_rn(v);
}
__global__ void k_splitr(const float* __restrict__ rel_emb) {
    int r = blockIdx.x, c = threadIdx.x;
    float v = (c < DIM) ? rel_emb[(size_t)r*DIM + c] * XS : 0.f;
    g_rs[r*XROW + c] = __float2half_rn(v);
}
// fc1^T: g_f1s[n][k] with k = seg*256+kc -> fc1[(seg*200+kc)][n]
__global__ void k_splitf(const float* __restrict__ fc1) {
    int idx = blockIdx.x*blockDim.x + threadIdx.x;
    if (idx >= HID*FROW) return;
    int n = idx / FROW, k = idx % FROW;
    int seg = k >> 8, kc = k & 255;
    float v = (kc < DIM) ? fc1[(size_t)(seg*DIM + kc)*HID + n] * WS : 0.f;
    g_f1s[(size_t)n*FROW + k] = __float2half_rn(v);
}
__global__ void k_outinit(float* __restrict__ out, const float* __restrict__ fc2b) {
    int i = blockIdx.x*blockDim.x + threadIdx.x;
    if (i < NQ) out[i] = fc2b[0];
}

// ---------------- edge gather-GEMM-scatter ----------------
__global__ void __launch_bounds__(512, 2)
k_edge(const __half* __restrict__ xs, const __half* __restrict__ wsl,
       const int* __restrict__ snd, const int* __restrict__ rcv,
       const int* __restrict__ relt) {
    extern __shared__ __align__(16) char sm[];
    uint32_t sb = smem_u32(sm);
    int* s_src = (int*)(sm + OFF_SRC);
    int* s_rcv = (int*)(sm + OFF_RCV);
    int tid = threadIdx.x, lane = tid & 31, w = tid >> 5;

    int e0 = g_perm[blockIdx.x*BM];
    if (e0 < 0) return;
    int rel = relt[e0];
    if (tid < BM) {
        int e = g_perm[blockIdx.x*BM + tid];
        int sv = 0, rv = -1;
        if (e >= 0) { sv = snd[e]; rv = rcv[e]; }
        s_src[tid] = sv; s_rcv[tid] = rv;
    }
    __syncthreads();

    const __half* wr = wsl + (size_t)rel * (256*XROW);
    int n0 = blockIdx.y * BM;
    int nlim = DIM - n0; if (nlim > BM) nlim = BM;
    int wm = (w & 3)*32, wn = (w >> 2)*32;
    int grp = lane >> 2, qid = lane & 3;

    float acc[2][4][4];
#pragma unroll
    for (int a = 0; a < 2; ++a)
#pragma unroll
        for (int b = 0; b < 4; ++b)
#pragma unroll
            for (int c = 0; c < 4; ++c) acc[a][b][c] = 0.f;

#define E_ISSUE(s, st)                                                           \
    {                                                                            \
        for (int j = tid; j < 1024; j += 512) {                                  \
            int row = (j >> 2) & 127, ch = j & 3;                                \
            if (j < 512) {                                                       \
                cpa16(sb + (st)*A_STG + row*80 + ch*16,                          \
                      xs + (size_t)s_src[row]*XROW + (s)*32 + ch*8);             \
            } else {                                                             \
                cpa16(sb + OFF_B + (st)*B_STG + row*80 + ch*16,                  \
                      wr + (size_t)(n0 + row)*XROW + (s)*32 + ch*8);             \
            }                                                                    \
        }                                                                        \
        cpa_commit();                                                            \
    }

    E_ISSUE(0, 0);
    E_ISSUE(1, 1);
#pragma unroll
    for (int s = 0; s < NSLAB; ++s) {
        if (s + 1 < NSLAB) cpa_wait1(); else cpa_wait0();
        __syncthreads();
        if (s + 2 < NSLAB) E_ISSUE(s + 2, (s + 2) % 3);
        slab_mma(sb, s % 3, wm, wn, lane, nlim, acc);
    }
#undef E_ISSUE

#pragma unroll
    for (int mi = 0; mi < 2; ++mi) {
        int r_e = wm + mi*16 + grp;
        int rv_e = s_rcv[r_e], rv_o = s_rcv[r_e + 8];
#pragma unroll
        for (int nj = 0; nj < 4; ++nj) {
            if (wn + nj*8 >= nlim) continue;
            float* c = acc[mi][nj];
            float e0f = __shfl_xor_sync(0xffffffffu, c[0], 1);
            float e1f = __shfl_xor_sync(0xffffffffu, c[1], 1);
            float e2f = __shfl_xor_sync(0xffffffffu, c[2], 1);
            float e3f = __shfl_xor_sync(0xffffffffu, c[3], 1);
            int colb = n0 + wn + nj*8 + (qid & ~1)*2;
            if ((qid & 1) == 0) {
                if (rv_e >= 0)
                    red4(g_agg + (size_t)rv_e*DIM + colb,
                         c[0]*SCALE_INV, c[1]*SCALE_INV, e0f*SCALE_INV, e1f*SCALE_INV);
            } else {
                if (rv_o >= 0)
                    red4(g_agg + (size_t)rv_o*DIM + colb,
                         e2f*SCALE_INV, e3f*SCALE_INV, c[2]*SCALE_INV, c[3]*SCALE_INV);
            }
        }
    }
}

// ---------------- dense GEMM (gate-merged via blockIdx.z) ----------------
__global__ void __launch_bounds__(512, 2)
k_dense(const __half* __restrict__ Axs, const __half* __restrict__ Bws,
        const __half* __restrict__ Axs2, const __half* __restrict__ Bws2,
        int M, int mode, int Nvalid,
        float* __restrict__ C, float* __restrict__ C2, int ldC,
        const float* __restrict__ agg, const float* __restrict__ dinv,
        const float* __restrict__ bias, __half* __restrict__ out_xs) {
    extern __shared__ __align__(16) char sm[];
    uint32_t sb = smem_u32(sm);
    if (blockIdx.z) { Axs = Axs2; Bws = Bws2; C = C2; }
    int tid = threadIdx.x, lane = tid & 31, w = tid >> 5;
    int m0 = blockIdx.x * BM;
    int n0 = blockIdx.y * BM;
    int nlim = Nvalid - n0; if (nlim > BM) nlim = BM; if (nlim < 0) nlim = 0;
    int wm = (w & 3)*32, wn = (w >> 2)*32;
    int grp = lane >> 2, qid = lane & 3;

    float acc[2][4][4];
#pragma unroll
    for (int a = 0; a < 2; ++a)
#pragma unroll
        for (int b = 0; b < 4; ++b)
#pragma unroll
            for (int c = 0; c < 4; ++c) acc[a][b][c] = 0.f;

#define D_ISSUE(s, st)                                                           \
    {                                                                            \
        for (int j = tid; j < 1024; j += 512) {                                  \
            int row = (j >> 2) & 127, ch = j & 3;                                \
            if (j < 512) {                                                       \
                int gm = m0 + row; if (gm >= M) gm = 0;                          \
                cpa16(sb + (st)*A_STG + row*80 + ch*16,                          \
                      Axs + (size_t)gm*XROW + (s)*32 + ch*8);                    \
            } else {                                                             \
                cpa16(sb + OFF_B + (st)*B_STG + row*80 + ch*16,                  \
                      Bws + (size_t)(n0 + row)*XROW + (s)*32 + ch*8);            \
            }                                                                    \
        }                                                                        \
        cpa_commit();                                                            \
    }

    D_ISSUE(0, 0);
    D_ISSUE(1, 1);
#pragma unroll
    for (int s = 0; s < NSLAB; ++s) {
        if (s + 1 < NSLAB) cpa_wait1(); else cpa_wait0();
        __syncthreads();
        if (s + 2 < NSLAB) D_ISSUE(s + 2, (s + 2) % 3);
        slab_mma(sb, s % 3, wm, wn, lane, nlim, acc);
    }
#undef D_ISSUE

#pragma unroll
    for (int mi = 0; mi < 2; ++mi) {
        int r0 = m0 + wm + mi*16 + grp;
        int r1 = r0 + 8;
#pragma unroll
        for (int nj = 0; nj < 4; ++nj) {
            if (wn + nj*8 >= nlim) continue;
            int col = n0 + wn + nj*8 + qid*2;
            float* c = acc[mi][nj];
            if (mode == 0) {
                if (col >= Nvalid) continue;
                if (r0 < M) *(float2*)(C + (size_t)r0*ldC + col) =
                    make_float2(c[0]*SCALE_INV, c[1]*SCALE_INV);
                if (r1 < M) *(float2*)(C + (size_t)r1*ldC + col) =
                    make_float2(c[2]*SCALE_INV, c[3]*SCALE_INV);
            } else {
#pragma unroll
                for (int h = 0; h < 2; ++h) {
                    int row = h ? r1 : r0;
                    if (row >= M) continue;
                    float v0 = 0.f, v1 = 0.f;
                    if (col < DIM) {
                        float dv = dinv[row];
                        float a0 = agg[(size_t)row*DIM + col]*dv + bias[col];
                        float a1 = agg[(size_t)row*DIM + col + 1]*dv + bias[col + 1];
                        v0 = fmaxf(c[h*2+0]*SCALE_INV + a0, 0.f) * XS;
                        v1 = fmaxf(c[h*2+1]*SCALE_INV + a1, 0.f) * XS;
                    }
                    *(__half2*)(out_xs + (size_t)row*XROW + col) =
                        __halves2half2(__float2half_rn(v0), __float2half_rn(v1));
                }
            }
        }
    }
}

__global__ void k_gru(const float* __restrict__ bg) {
    int idx = blockIdx.x*blockDim.x + threadIdx.x;
    if (idx >= N_ENT*DIM) return;
    int n = idx / DIM, c = idx % DIM;
    size_t b = (size_t)n*D3;
    float r  = sigf(g_xW[b + c]        + g_hU[b + c]        + bg[c]);
    float z  = sigf(g_xW[b + DIM + c]  + g_hU[b + DIM + c]  + bg[DIM + c]);
    float hu3 = g_hU[b + 2*DIM + c];
    float ht = tanhf(g_xW[b + 2*DIM + c] + hu3 + bg[2*DIM + c] + r * hu3);
    float h0 = g_h[idx];
    float hn = (1.f - z)*h0 + z*ht;
    g_h[idx] = hn;
    g_hs[(size_t)n*XROW + c] = __float2half_rn(hn * XS);
}

// ---------------- tensor-core scorer ----------------
__global__ void __launch_bounds__(512, 2)
k_scoreT(const int* __restrict__ triples, const float* __restrict__ b1,
         const float* __restrict__ fc2, float* __restrict__ out) {
    extern __shared__ __align__(16) char sm[];
    uint32_t sb = smem_u32(sm);
    int* s_s = (int*)(sm + OFF_I0);
    int* s_r = (int*)(sm + OFF_I1);
    int* s_o = (int*)(sm + OFF_I2);
    int tid = threadIdx.x, lane = tid & 31, w = tid >> 5;
    int m0 = blockIdx.x * BM;
    int n0 = blockIdx.y * BM;
    int wm = (w & 3)*32, wn = (w >> 2)*32;
    int grp = lane >> 2, qid = lane & 3;

    if (tid < BM) {
        s_s[tid] = triples[(m0 + tid)*3 + 0];
        s_r[tid] = triples[(m0 + tid)*3 + 1];
        s_o[tid] = triples[(m0 + tid)*3 + 2];
    }
    __syncthreads();

    float acc[2][4][4];
#pragma unroll
    for (int a = 0; a < 2; ++a)
#pragma unroll
        for (int b = 0; b < 4; ++b)
#pragma unroll
            for (int c = 0; c < 4; ++c) acc[a][b][c] = 0.f;

#define S_ISSUE(s, st)                                                           \
    {                                                                            \
        int ss = (s);                                                            \
        int seg = ss >> 3, sk = (ss & 7)*32;                                     \
        for (int j = tid; j < 1024; j += 512) {                                  \
            int row = (j >> 2) & 127, ch = j & 3;                                \
            if (j < 512) {                                                       \
                const __half* base;                                              \
                if (seg == 0)      base = g_hs + (size_t)s_s[row]*XROW;          \
                else if (seg == 1) base = g_rs + (size_t)s_r[row]*XROW;          \
                else               base = g_hs + (size_t)s_o[row]*XROW;          \
                cpa16(sb + (st)*A_STG + row*80 + ch*16, base + sk + ch*8);       \
            } else {                                                             \
                cpa16(sb + OFF_B + (st)*B_STG + row*80 + ch*16,                  \
                      g_f1s + (size_t)(n0 + row)*FROW + ss*32 + ch*8);           \
            }                                                                    \
        }                                                                        \
        cpa_commit();                                                            \
    }

    S_ISSUE(0, 0);
    S_ISSUE(1, 1);
    for (int s = 0; s < SSLAB; ++s) {
        if (s + 1 < SSLAB) cpa_wait1(); else cpa_wait0();
        __syncthreads();
        if (s + 2 < SSLAB) S_ISSUE(s + 2, (s + 2) % 3);
        slab_mma(sb, s % 3, wm, wn, lane, BM, acc);
    }
#undef S_ISSUE

#pragma unroll
    for (int mi = 0; mi < 2; ++mi) {
        int r0 = m0 + wm + mi*16 + grp;
        float p0 = 0.f, p1 = 0.f;
#pragma unroll
        for (int nj = 0; nj < 4; ++nj) {
            int col = n0 + wn + nj*8 + qid*2;
            float* c = acc[mi][nj];
            float b0 = b1[col], b2 = b1[col+1];
            float f0 = fc2[col], f2 = fc2[col+1];
            p0 += fmaxf(c[0]*SCALE_INV + b0, 0.f)*f0 + fmaxf(c[1]*SCALE_INV + b2, 0.f)*f2;
            p1 += fmaxf(c[2]*SCALE_INV + b0, 0.f)*f0 + fmaxf(c[3]*SCALE_INV + b2, 0.f)*f2;
        }
        p0 += __shfl_down_sync(0xffffffffu, p0, 2, 4);
        p0 += __shfl_down_sync(0xffffffffu, p0, 1, 4);
        p1 += __shfl_down_sync(0xffffffffu, p1, 2, 4);
        p1 += __shfl_down_sync(0xffffffffu, p1, 1, 4);
        if (qid == 0) {
            atomicAdd(out + r0, p0);
            atomicAdd(out + r0 + 8, p1);
        }
    }
}

// ---------------- host ----------------
extern "C" void kernel_launch(void* const* d_in, const int* in_sizes, int n_in,
                              void* d_out, int out_size) {
    const float* entity_emb = (const float*)d_in[0];
    const float* basis      = (const float*)d_in[1];
    const float* coeff      = (const float*)d_in[2];
    const float* self_w     = (const float*)d_in[3];
    const float* bias       = (const float*)d_in[4];
    const float* W_gates    = (const float*)d_in[5];
    const float* U_gates    = (const float*)d_in[6];
    const float* b_gates    = (const float*)d_in[7];
    const float* rel_emb    = (const float*)d_in[8];
    const float* fc1        = (const float*)d_in[9];
    const float* fc1_b      = (const float*)d_in[10];
    const float* fc2        = (const float*)d_in[11];
    const float* fc2_b      = (const float*)d_in[12];
    const int*   senders    = (const int*)d_in[13];
    const int*   receivers  = (const int*)d_in[14];
    const int*   rel_types  = (const int*)d_in[15];
    const int*   triples    = (const int*)d_in[16];
    float* out = (float*)d_out;

    cudaFuncSetAttribute(k_edge,   cudaFuncAttributeMaxDynamicSharedMemorySize, P_SMEM);
    cudaFuncSetAttribute(k_dense,  cudaFuncAttributeMaxDynamicSharedMemorySize, P_SMEM);
    cudaFuncSetAttribute(k_scoreT, cudaFuncAttributeMaxDynamicSharedMemorySize, S_SMEM);

    float *p_relw, *p_h, *p_agg, *p_dinv, *p_xW, *p_hU;
    __half *p_hs, *p_xs1, *p_xs2, *p_ws, *p_sws, *p_gws, *p_gus;
    cudaGetSymbolAddress((void**)&p_relw, g_relw);
    cudaGetSymbolAddress((void**)&p_h,    g_h);
    cudaGetSymbolAddress((void**)&p_agg,  g_agg);
    cudaGetSymbolAddress((void**)&p_dinv, g_deginv);
    cudaGetSymbolAddress((void**)&p_xW,   g_xW);
    cudaGetSymbolAddress((void**)&p_hU,   g_hU);
    cudaGetSymbolAddress((void**)&p_hs,   g_hs);
    cudaGetSymbolAddress((void**)&p_xs1,  g_xs1);
    cudaGetSymbolAddress((void**)&p_xs2,  g_xs2);
    cudaGetSymbolAddress((void**)&p_ws,   g_ws);
    cudaGetSymbolAddress((void**)&p_sws,  g_sws);
    cudaGetSymbolAddress((void**)&p_gws,  g_gws);
    cudaGetSymbolAddress((void**)&p_gus,  g_gus);

    k_relw<<<(NL*DIM*DIM + 255)/256, 256>>>(basis, coeff);
    k_splitw<<<dim3(256, 1, NL*RR), 256>>>(p_relw, p_ws, DIM, DIM,
                                           (size_t)DIM*DIM, (size_t)256*XROW);
    k_splitw<<<dim3(256, 1, NL), 256>>>(self_w, p_sws, DIM, DIM,
                                        (size_t)DIM*DIM, (size_t)256*XROW);
    k_splitw<<<dim3(GNPAD, 1, 1), 256>>>(W_gates, p_gws, D3, D3, 0, 0);
    k_splitw<<<dim3(GNPAD, 1, 1), 256>>>(U_gates, p_gus, D3, D3, 0, 0);
    k_splitx<<<(N_ENT*256 + 255)/256, 256>>>(entity_emb, p_hs);
    k_splitr<<<RR, 256>>>(rel_emb);
    k_splitf<<<(HID*FROW + 255)/256, 256>>>(fc1);
    k_copy<<<1024, 256>>>(p_h, entity_emb, N_ENT*DIM);

    for (int t = 0; t < NT; ++t) {
        const int* snd = senders   + (size_t)t*NE;
        const int* rcv = receivers + (size_t)t*NE;
        const int* rlt = rel_types + (size_t)t*NE;

        k_setup<<<512, 256>>>();
        k_prep<<<512, 256>>>(rcv, rlt);
        k_scan_dinv<<<(N_ENT + 255)/256, 256>>>();
        k_scatter<<<512, 256>>>(rlt);

        const __half* xin = p_hs;
        __half* xout[2] = { p_xs1, p_xs2 };
        for (int l = 0; l < NL; ++l) {
            k_zerof<<<1024, 256>>>(p_agg, N_ENT*DIM);
            k_edge<<<dim3(EGRID, 2), 512, P_SMEM>>>(xin, p_ws + (size_t)l*RR*256*XROW,
                                                    snd, rcv, rlt);
            k_dense<<<dim3(MTILES, 2), 512, P_SMEM>>>(
                xin, p_sws + (size_t)l*256*XROW, xin, p_sws + (size_t)l*256*XROW,
                N_ENT, 1, DIM,
                nullptr, nullptr, 0, p_agg, p_dinv, bias + (size_t)l*DIM, xout[l]);
            xin = xout[l];
        }
        k_dense<<<dim3(MTILES, 5, 2), 512, P_SMEM>>>(
            p_xs2, p_gws, p_hs, p_gus, N_ENT, 0, D3,
            p_xW, p_hU, D3, nullptr, nullptr, nullptr, nullptr);
        k_gru<<<(N_ENT*DIM + 255)/256, 256>>>(b_gates);
    }

    k_outinit<<<(NQ + 255)/256, 256>>>(out, fc2_b);
    k_scoreT<<<dim3(NQ/BM, 2), 512, S_SMEM>>>(triples, fc1_b, fc2, out);
}